// round 13
// baseline (speedup 1.0000x reference)
#include <cuda_runtime.h>
#include <math.h>
#include <float.h>

#define OUTD    12
#define N_VOX   1728              // 12*12*12
#define N_ROIS  128
#define N_PTS   160000
#define NCH     64
#define KMAX    64                // cap on points per (roi,voxel); fallback handles overflow
#define NRV     (N_ROIS * N_VOX)  // 221184 = 864 * 256
#define NF4     (NRV * NCH / 4)   // 3,538,944 float4s in output

static_assert(N_PTS % 256 == 0, "exact build grid");
static_assert(NRV % 256 == 0, "exact pool grid");

// Scratch (__device__ globals = sanctioned scratch; zero-initialized at load).
// d_meta self-cleaned by pool_kernel each run -> invariant holds across replays.
// d_meta[rv] = {count, first_pid}. d_list used only from slot 1 (n>=2).
__device__ __align__(8) int2 d_meta[NRV];
__device__ __align__(16) int d_list[NRV * KMAX];

// ---------------------------------------------------------------------------
// Kernel 1: build + INTERLEAVED zero-fill (R12 winning mechanism, unchanged
// except meta packing). One guarded STG.128 of zeros per 4-ROI group: the
// store queue drains under ~30 instr of compute per store, hiding the 56.6MB
// LTS drain beneath the ROI loop.
// ---------------------------------------------------------------------------
__global__ __launch_bounds__(256) void build_fill_kernel(
    const float* __restrict__ rois, const float* __restrict__ pts,
    float* __restrict__ out)
{
    __shared__ float4 sA[N_ROIS];  // {cx, cy, r2_margin, cz}
    __shared__ float4 sB[N_ROIS];  // {cosa, sina, hdx, hdy}
    __shared__ float4 sC[N_ROIS];  // {hdz, vx, vy, vz}

    int t = threadIdx.x;
    int p = blockIdx.x * blockDim.x + t;      // always < N_PTS (exact grid)

    float px = pts[3 * p + 0];
    float py = pts[3 * p + 1];
    float pz = pts[3 * p + 2];

    if (t < N_ROIS) {
        const float* R = rois + t * 7;
        float cx = R[0], cy = R[1], cz = R[2];
        float dx = R[3], dy = R[4], dz = R[5];
        float ry = R[6];
        float hdx = dx * 0.5f, hdy = dy * 0.5f, hdz = dz * 0.5f;
        float r2  = (hdx * hdx + hdy * hdy) * 1.0002f + 1e-6f;  // conservative
        float ca  = cosf(-ry), sa = sinf(-ry);
        sA[t] = make_float4(cx, cy, r2, cz);
        sB[t] = make_float4(ca, sa, hdx, hdy);
        sC[t] = make_float4(hdz, dx / (float)OUTD, dy / (float)OUTD, dz / (float)OUTD);
    }
    __syncthreads();

    float4* o4 = (float4*)out;
    const float4 z = make_float4(0.f, 0.f, 0.f, 0.f);
    int fi = p;                                // fill cursor, stride N_PTS

    for (int rr = 0; rr < N_ROIS; rr += 4) {
        // One interleaved zero store per 4-ROI group (guarded; 32 groups
        // cover the <=23 stores this thread owes).
        if (fi < NF4) { __stcs(&o4[fi], z); fi += N_PTS; }

        #pragma unroll
        for (int u = 0; u < 4; u++) {
            int r = rr + u;
            float4 A = sA[r];                 // broadcast LDS.128 (uniform r)
            float sx = px - A.x;
            float sy = py - A.y;
            float d2 = sx * sx + sy * sy;
            if (d2 > A.z) continue;           // ~99.8% rejected here

            float sz = pz - A.w;
            float4 B = sB[r];
            float4 C = sC[r];
            float lx = sx * B.x - sy * B.y;   // rotate into roi frame (angle = -ry)
            float ly = sx * B.y + sy * B.x;
            bool in_box = (lx > -B.z) && (lx < B.z) &&
                          (ly > -B.w) && (ly < B.w) &&
                          (fabsf(sz - C.x) <= C.x);
            if (!in_box) continue;

            int xi = min(OUTD - 1, max(0, (int)floorf((lx + B.z) / C.y)));
            int yi = min(OUTD - 1, max(0, (int)floorf((ly + B.w) / C.z)));
            int zi = min(OUTD - 1, max(0, (int)floorf(sz / C.w)));
            int rv = r * N_VOX + xi * (OUTD * OUTD) + yi * OUTD + zi;
            int c = atomicAdd(&d_meta[rv].x, 1);
            if (c == 0)          d_meta[rv].y = p;             // unique writer
            else if (c < KMAX)   d_list[rv * KMAX + c] = p;    // slots 1..
        }
    }
    // Safety tail (never taken for this geometry: 23 <= 32 slots).
    for (; fi < NF4; fi += N_PTS) __stcs(&o4[fi], z);
}

// ---------------------------------------------------------------------------
// Kernel 2: gather pool with fused meta. Coalesced int2 meta scan into smem
// (+ self-clean of dirty entries), ballot-compaction of non-empty voxels.
// Per entry the warp reads {n, pid0} from SMEM (no global metadata hop) and
// prefetches the FEATURE row of the next entry. n==1 (~94% of entries):
// output = feature row directly -> single global hop. n>=2: list slots 1..;
// n>KMAX: full-rescan fallback.
// ---------------------------------------------------------------------------
__global__ __launch_bounds__(256, 6) void pool_kernel(
    const float* __restrict__ rois, const float* __restrict__ pts,
    const float* __restrict__ feat, float* __restrict__ out)
{
    __shared__ int2 sMeta[256];
    __shared__ int  sQ[256];
    __shared__ int  sQn;

    int t    = threadIdx.x;
    int lane = t & 31;
    int wid  = t >> 5;
    int vblock = blockIdx.x << 8;             // first voxel of this block

    int2 me = d_meta[vblock + t];             // coalesced 2KB burst
    sMeta[t] = me;
    if (me.x) d_meta[vblock + t] = make_int2(0, 0);   // self-clean dirty only
    if (t == 0) sQn = 0;
    __syncthreads();

    // Ballot-compact non-empty local voxel ids into sQ.
    unsigned m = __ballot_sync(0xffffffffu, me.x > 0);
    int base = 0;
    if (lane == 0 && m) base = atomicAdd(&sQn, __popc(m));
    base = __shfl_sync(0xffffffffu, base, 0);
    if (me.x > 0) sQ[base + __popc(m & ((1u << lane) - 1u))] = t;
    __syncthreads();
    int qn = sQn;

    // Rotating 2-deep pipeline: prefetch the NEXT entry's feature row
    // (not just metadata) while finishing the current one.
    int i = wid;
    int cGv = -1, cN = 0;
    float2 cV = make_float2(0.f, 0.f);
    if (i < qn) {
        int lv = sQ[i];
        int2 mm = sMeta[lv];                  // LDS: {n, pid0}
        cGv = vblock + lv;
        cN  = mm.x;
        cV  = ((const float2*)(feat + (size_t)mm.y * NCH))[lane];  // issue LDG
    }
    while (cGv >= 0) {
        // Prefetch next entry.
        int nGv = -1, nN = 0;
        float2 nV = make_float2(0.f, 0.f);
        i += 8;
        if (i < qn) {
            int lv = sQ[i];
            int2 mm = sMeta[lv];
            nGv = vblock + lv;
            nN  = mm.x;
            nV  = ((const float2*)(feat + (size_t)mm.y * NCH))[lane];
        }

        float mx0 = cV.x, mx1 = cV.y;         // n==1: result is the row itself
        if (cN > 1) {
            // Slow path (~6%): pids 2..n come from list slots 1..
            int mm2 = min(cN, KMAX);
            const int* lst = &d_list[(size_t)cGv * KMAX];
            int4 q4 = *(const int4*)lst;      // slots 0..3 (slot0 unused)
            {
                float2 v1, v2, v3;
                if (mm2 > 1) v1 = ((const float2*)(feat + (size_t)q4.y * NCH))[lane];
                if (mm2 > 2) v2 = ((const float2*)(feat + (size_t)q4.z * NCH))[lane];
                if (mm2 > 3) v3 = ((const float2*)(feat + (size_t)q4.w * NCH))[lane];
                if (mm2 > 1) { mx0 = fmaxf(mx0, v1.x); mx1 = fmaxf(mx1, v1.y); }
                if (mm2 > 2) { mx0 = fmaxf(mx0, v2.x); mx1 = fmaxf(mx1, v2.y); }
                if (mm2 > 3) { mx0 = fmaxf(mx0, v3.x); mx1 = fmaxf(mx1, v3.y); }
            }
            for (int j = 4; j < mm2; j++) {
                int pid = lst[j];
                float2 v = ((const float2*)(feat + (size_t)pid * NCH))[lane];
                mx0 = fmaxf(mx0, v.x);
                mx1 = fmaxf(mx1, v.y);
            }
            if (cN > KMAX) {
                // Correctness fallback (statistically never taken).
                int r = cGv / N_VOX, vox = cGv % N_VOX;
                int xi = vox / (OUTD * OUTD), yi = (vox / OUTD) % OUTD, zi = vox % OUTD;
                const float* R = rois + r * 7;
                float cx = R[0], cy = R[1], cz = R[2];
                float dx = R[3], dy = R[4], dz = R[5];
                float ry = R[6];
                float hdx = dx * 0.5f, hdy = dy * 0.5f, hdz = dz * 0.5f;
                float ca = cosf(-ry), sa = sinf(-ry);
                float vx = dx / (float)OUTD, vy = dy / (float)OUTD, vz = dz / (float)OUTD;
                for (int bb = 0; bb < N_PTS; bb += 32) {
                    int pp = bb + lane;
                    bool hit = false;
                    {
                        float sx = pts[3 * pp + 0] - cx;
                        float sy = pts[3 * pp + 1] - cy;
                        float szz = pts[3 * pp + 2] - cz;
                        float lx = sx * ca - sy * sa;
                        float ly = sx * sa + sy * ca;
                        if ((lx > -hdx) && (lx < hdx) && (ly > -hdy) && (ly < hdy) &&
                            (fabsf(szz - hdz) <= hdz)) {
                            int xa = min(OUTD - 1, max(0, (int)floorf((lx + hdx) / vx)));
                            int ya = min(OUTD - 1, max(0, (int)floorf((ly + hdy) / vy)));
                            int za = min(OUTD - 1, max(0, (int)floorf(szz / vz)));
                            hit = (xa == xi) && (ya == yi) && (za == zi);
                        }
                    }
                    unsigned mk = __ballot_sync(0xffffffffu, hit);
                    while (mk) {
                        int src = __ffs(mk) - 1;
                        mk &= mk - 1;
                        int pid = bb + src;
                        float2 v = ((const float2*)(feat + (size_t)pid * NCH))[lane];
                        mx0 = fmaxf(mx0, v.x);
                        mx1 = fmaxf(mx1, v.y);
                    }
                }
            }
        }

        __stcs(&((float2*)(out + (size_t)cGv * NCH))[lane], make_float2(mx0, mx1));

        cGv = nGv; cN = nN; cV = nV;          // rotate pipeline
    }
}

// ---------------------------------------------------------------------------
extern "C" void kernel_launch(void* const* d_in, const int* in_sizes, int n_in,
                              void* d_out, int out_size)
{
    const float* rois = (const float*)d_in[0];       // (128, 7)
    const float* pts  = (const float*)d_in[1];       // (160000, 3)
    const float* feat = (const float*)d_in[2];       // (160000, 64)
    float* out = (float*)d_out;                      // (128, 12, 12, 12, 64)

    build_fill_kernel<<<N_PTS / 256, 256>>>(rois, pts, out); // interleaved fill+build
    pool_kernel<<<NRV / 256, 256>>>(rois, pts, feat, out);   // fused-meta pool
}

// round 14
// speedup vs baseline: 1.3066x; 1.3066x over previous
#include <cuda_runtime.h>
#include <math.h>
#include <float.h>

#define OUTD    12
#define N_VOX   1728              // 12*12*12
#define N_ROIS  128
#define N_PTS   160000
#define NCH     64
#define KMAX    64                // cap on points per (roi,voxel); fallback handles overflow
#define NRV     (N_ROIS * N_VOX)  // 221184
#define NF4     (NRV * NCH / 4)   // 3,538,944 float4s in output

#define POOL_BLOCKS 888
#define POOL_WARPS  (POOL_BLOCKS * 8)

static_assert(N_PTS % 256 == 0, "exact build grid");

// Scratch (__device__ globals = sanctioned scratch; zero-initialized at load).
// Invariants restored every replay: d_count zeroed per entry by pool,
// d_qn/d_done reset by last pool block out. d_queue may stay dirty (gated by qn).
__device__ int d_count[NRV];
__device__ __align__(16) int d_list[NRV * KMAX];   // slots 1.. used (slot0 = queue)
__device__ int d_qn;
__device__ int d_done;
__device__ __align__(8) int2 d_queue[NRV];         // {rv, first_pid}

// ---------------------------------------------------------------------------
// Kernel 1: build + INTERLEAVED zero-fill (R12 winning form). One guarded
// STG.128 of zeros per 4-ROI group: the store queue drains under ~30 instr
// of compute per store, hiding the 56.6MB LTS drain beneath the ROI loop.
// The unique first inserter pushes {rv, pid} onto the worklist (R9-proven
// cheap); later inserters go to list slots 1..KMAX-1.
// ---------------------------------------------------------------------------
__global__ __launch_bounds__(256) void build_fill_kernel(
    const float* __restrict__ rois, const float* __restrict__ pts,
    float* __restrict__ out)
{
    __shared__ float4 sA[N_ROIS];  // {cx, cy, r2_margin, cz}
    __shared__ float4 sB[N_ROIS];  // {cosa, sina, hdx, hdy}
    __shared__ float4 sC[N_ROIS];  // {hdz, vx, vy, vz}

    int t = threadIdx.x;
    int p = blockIdx.x * blockDim.x + t;      // always < N_PTS (exact grid)

    float px = pts[3 * p + 0];
    float py = pts[3 * p + 1];
    float pz = pts[3 * p + 2];

    if (t < N_ROIS) {
        const float* R = rois + t * 7;
        float cx = R[0], cy = R[1], cz = R[2];
        float dx = R[3], dy = R[4], dz = R[5];
        float ry = R[6];
        float hdx = dx * 0.5f, hdy = dy * 0.5f, hdz = dz * 0.5f;
        float r2  = (hdx * hdx + hdy * hdy) * 1.0002f + 1e-6f;  // conservative
        float ca  = cosf(-ry), sa = sinf(-ry);
        sA[t] = make_float4(cx, cy, r2, cz);
        sB[t] = make_float4(ca, sa, hdx, hdy);
        sC[t] = make_float4(hdz, dx / (float)OUTD, dy / (float)OUTD, dz / (float)OUTD);
    }
    __syncthreads();

    float4* o4 = (float4*)out;
    const float4 z = make_float4(0.f, 0.f, 0.f, 0.f);
    int fi = p;                                // fill cursor, stride N_PTS

    for (int rr = 0; rr < N_ROIS; rr += 4) {
        // One interleaved zero store per 4-ROI group (guarded; 32 groups
        // cover the <=23 stores this thread owes).
        if (fi < NF4) { __stcs(&o4[fi], z); fi += N_PTS; }

        #pragma unroll
        for (int u = 0; u < 4; u++) {
            int r = rr + u;
            float4 A = sA[r];                 // broadcast LDS.128 (uniform r)
            float sx = px - A.x;
            float sy = py - A.y;
            float d2 = sx * sx + sy * sy;
            if (d2 > A.z) continue;           // ~99.8% rejected here

            float sz = pz - A.w;
            float4 B = sB[r];
            float4 C = sC[r];
            float lx = sx * B.x - sy * B.y;   // rotate into roi frame (angle = -ry)
            float ly = sx * B.y + sy * B.x;
            bool in_box = (lx > -B.z) && (lx < B.z) &&
                          (ly > -B.w) && (ly < B.w) &&
                          (fabsf(sz - C.x) <= C.x);
            if (!in_box) continue;

            int xi = min(OUTD - 1, max(0, (int)floorf((lx + B.z) / C.y)));
            int yi = min(OUTD - 1, max(0, (int)floorf((ly + B.w) / C.z)));
            int zi = min(OUTD - 1, max(0, (int)floorf(sz / C.w)));
            int rv = r * N_VOX + xi * (OUTD * OUTD) + yi * OUTD + zi;
            int c = atomicAdd(&d_count[rv], 1);
            if (c == 0) {                     // unique first inserter
                int qi = atomicAdd(&d_qn, 1);
                d_queue[qi] = make_int2(rv, p);
            } else if (c < KMAX) {
                d_list[rv * KMAX + c] = p;    // slots 1..KMAX-1
            }
        }
    }
    // Safety tail (never taken for this geometry: 23 <= 32 slots).
    for (; fi < NF4; fi += N_PTS) __stcs(&o4[fi], z);
}

// ---------------------------------------------------------------------------
// Kernel 2: worklist pool with pid0 payload. Warps grid-stride the ~16K
// queue entries (~2.3/warp). Per entry the queue word carries {rv, pid0}:
// for n==1 (~94%) the chain is queue LDG -> feat LDG -> STG (count load in
// parallel, no list hop, no scan/compaction preamble). 2-deep rotation
// prefetches next entry's queue word + count + feature row. n>=2: list
// slots 1..; n>KMAX: full-rescan fallback. Counts self-cleaned per entry;
// last block out (ticket counter) resets d_qn/d_done.
// ---------------------------------------------------------------------------
__global__ __launch_bounds__(256, 6) void pool_kernel(
    const float* __restrict__ rois, const float* __restrict__ pts,
    const float* __restrict__ feat, float* __restrict__ out)
{
    int lane  = threadIdx.x & 31;
    int gwarp = blockIdx.x * 8 + (threadIdx.x >> 5);
    int qn    = d_qn;                          // uniform read

    int i = gwarp;
    int cRv = -1, cN = 0;
    float2 cV = make_float2(0.f, 0.f);
    if (i < qn) {
        int2 q = d_queue[i];
        cRv = q.x;
        cN  = d_count[q.x];                    // parallel with feat load
        cV  = ((const float2*)(feat + (size_t)q.y * NCH))[lane];
    }
    while (cRv >= 0) {
        // Prefetch next entry's whole chain.
        int nRv = -1, nN = 0;
        float2 nV = make_float2(0.f, 0.f);
        i += POOL_WARPS;
        if (i < qn) {
            int2 q = d_queue[i];
            nRv = q.x;
            nN  = d_count[q.x];
            nV  = ((const float2*)(feat + (size_t)q.y * NCH))[lane];
        }
        if (lane == 0) d_count[cRv] = 0;       // self-clean for next replay

        float mx0 = cV.x, mx1 = cV.y;          // n==1: row is the answer
        if (cN > 1) {
            int mm = min(cN, KMAX);
            const int* lst = &d_list[(size_t)cRv * KMAX];
            int4 q4 = *(const int4*)lst;       // slots 0..3 (slot0 unused)
            {
                float2 v1, v2, v3;
                if (mm > 1) v1 = ((const float2*)(feat + (size_t)q4.y * NCH))[lane];
                if (mm > 2) v2 = ((const float2*)(feat + (size_t)q4.z * NCH))[lane];
                if (mm > 3) v3 = ((const float2*)(feat + (size_t)q4.w * NCH))[lane];
                if (mm > 1) { mx0 = fmaxf(mx0, v1.x); mx1 = fmaxf(mx1, v1.y); }
                if (mm > 2) { mx0 = fmaxf(mx0, v2.x); mx1 = fmaxf(mx1, v2.y); }
                if (mm > 3) { mx0 = fmaxf(mx0, v3.x); mx1 = fmaxf(mx1, v3.y); }
            }
            for (int j = 4; j < mm; j++) {
                int pid = lst[j];
                float2 v = ((const float2*)(feat + (size_t)pid * NCH))[lane];
                mx0 = fmaxf(mx0, v.x);
                mx1 = fmaxf(mx1, v.y);
            }
            if (cN > KMAX) {
                // Correctness fallback (statistically never taken): rescan.
                int r = cRv / N_VOX, vox = cRv % N_VOX;
                int xi = vox / (OUTD * OUTD), yi = (vox / OUTD) % OUTD, zi = vox % OUTD;
                const float* R = rois + r * 7;
                float cx = R[0], cy = R[1], cz = R[2];
                float dx = R[3], dy = R[4], dz = R[5];
                float ry = R[6];
                float hdx = dx * 0.5f, hdy = dy * 0.5f, hdz = dz * 0.5f;
                float ca = cosf(-ry), sa = sinf(-ry);
                float vx = dx / (float)OUTD, vy = dy / (float)OUTD, vz = dz / (float)OUTD;
                for (int bb = 0; bb < N_PTS; bb += 32) {
                    int pp = bb + lane;
                    bool hit = false;
                    {
                        float sx = pts[3 * pp + 0] - cx;
                        float sy = pts[3 * pp + 1] - cy;
                        float szz = pts[3 * pp + 2] - cz;
                        float lx = sx * ca - sy * sa;
                        float ly = sx * sa + sy * ca;
                        if ((lx > -hdx) && (lx < hdx) && (ly > -hdy) && (ly < hdy) &&
                            (fabsf(szz - hdz) <= hdz)) {
                            int xa = min(OUTD - 1, max(0, (int)floorf((lx + hdx) / vx)));
                            int ya = min(OUTD - 1, max(0, (int)floorf((ly + hdy) / vy)));
                            int za = min(OUTD - 1, max(0, (int)floorf(szz / vz)));
                            hit = (xa == xi) && (ya == yi) && (za == zi);
                        }
                    }
                    unsigned mk = __ballot_sync(0xffffffffu, hit);
                    while (mk) {
                        int src = __ffs(mk) - 1;
                        mk &= mk - 1;
                        int pid = bb + src;
                        float2 v = ((const float2*)(feat + (size_t)pid * NCH))[lane];
                        mx0 = fmaxf(mx0, v.x);
                        mx1 = fmaxf(mx1, v.y);
                    }
                }
            }
        }

        __stcs(&((float2*)(out + (size_t)cRv * NCH))[lane], make_float2(mx0, mx1));

        cRv = nRv; cN = nN; cV = nV;           // rotate pipeline
    }

    // Last block out resets the worklist counter (race-free; ticket counter).
    __syncthreads();
    if (threadIdx.x == 0) {
        __threadfence();
        int ticket = atomicAdd(&d_done, 1);
        if (ticket == POOL_BLOCKS - 1) {
            d_qn = 0;
            d_done = 0;
        }
    }
}

// ---------------------------------------------------------------------------
extern "C" void kernel_launch(void* const* d_in, const int* in_sizes, int n_in,
                              void* d_out, int out_size)
{
    const float* rois = (const float*)d_in[0];       // (128, 7)
    const float* pts  = (const float*)d_in[1];       // (160000, 3)
    const float* feat = (const float*)d_in[2];       // (160000, 64)
    float* out = (float*)d_out;                      // (128, 12, 12, 12, 64)

    build_fill_kernel<<<N_PTS / 256, 256>>>(rois, pts, out); // interleaved fill+build+queue
    pool_kernel<<<POOL_BLOCKS, 256>>>(rois, pts, feat, out); // worklist pool (pid0 payload)
}

// round 15
// speedup vs baseline: 1.3793x; 1.0556x over previous
#include <cuda_runtime.h>
#include <math.h>
#include <float.h>

#define OUTD    12
#define N_VOX   1728              // 12*12*12
#define N_ROIS  128
#define N_PTS   160000
#define NCH     64
#define KMAX    64                // cap on points per (roi,voxel); fallback handles overflow
#define NRV     (N_ROIS * N_VOX)  // 221184
#define NF4     (NRV * NCH / 4)   // 3,538,944 float4s in output

#define POOL_BLOCKS 888
#define POOL_WARPS  (POOL_BLOCKS * 8)
#define QBUF        2048          // per-block smem queue capacity (expected ~27 used)

static_assert(N_PTS % 256 == 0, "exact build grid");

// Scratch (__device__ globals = sanctioned scratch; zero-initialized at load).
// Invariants restored every replay: d_count zeroed per entry by pool,
// d_qn/d_done reset by last pool block out. d_queue may stay dirty (gated by qn).
__device__ int d_count[NRV];
__device__ __align__(16) int d_list[NRV * KMAX];   // slots 1.. used (slot0 = queue)
__device__ int d_qn;
__device__ int d_done;
__device__ __align__(8) int2 d_queue[NRV];         // {rv, first_pid}

// ---------------------------------------------------------------------------
// Kernel 1: build + INTERLEAVED zero-fill (R12 winning form) + SMEM-BATCHED
// worklist. One guarded STG.128 of zeros per 4-ROI group hides the 56.6MB
// LTS drain under the ROI loop. First-inserters push {rv,pid} into a smem
// buffer (no global atomic hotspot); at the end ONE atomicAdd per block
// reserves a d_queue range and entries are copied out coalesced.
// ---------------------------------------------------------------------------
__global__ __launch_bounds__(256) void build_fill_kernel(
    const float* __restrict__ rois, const float* __restrict__ pts,
    float* __restrict__ out)
{
    __shared__ float4 sA[N_ROIS];  // {cx, cy, r2_margin, cz}
    __shared__ float4 sB[N_ROIS];  // {cosa, sina, hdx, hdy}
    __shared__ float4 sC[N_ROIS];  // {hdz, vx, vy, vz}
    __shared__ int2   sQbuf[QBUF];
    __shared__ int    sQcnt;
    __shared__ int    sGbase;

    int t = threadIdx.x;
    int p = blockIdx.x * blockDim.x + t;      // always < N_PTS (exact grid)

    float px = pts[3 * p + 0];
    float py = pts[3 * p + 1];
    float pz = pts[3 * p + 2];

    if (t == 0) sQcnt = 0;
    if (t < N_ROIS) {
        const float* R = rois + t * 7;
        float cx = R[0], cy = R[1], cz = R[2];
        float dx = R[3], dy = R[4], dz = R[5];
        float ry = R[6];
        float hdx = dx * 0.5f, hdy = dy * 0.5f, hdz = dz * 0.5f;
        float r2  = (hdx * hdx + hdy * hdy) * 1.0002f + 1e-6f;  // conservative
        float ca  = cosf(-ry), sa = sinf(-ry);
        sA[t] = make_float4(cx, cy, r2, cz);
        sB[t] = make_float4(ca, sa, hdx, hdy);
        sC[t] = make_float4(hdz, dx / (float)OUTD, dy / (float)OUTD, dz / (float)OUTD);
    }
    __syncthreads();

    float4* o4 = (float4*)out;
    const float4 z = make_float4(0.f, 0.f, 0.f, 0.f);
    int fi = p;                                // fill cursor, stride N_PTS

    for (int rr = 0; rr < N_ROIS; rr += 4) {
        // One interleaved zero store per 4-ROI group (guarded; 32 groups
        // cover the <=23 stores this thread owes).
        if (fi < NF4) { __stcs(&o4[fi], z); fi += N_PTS; }

        #pragma unroll
        for (int u = 0; u < 4; u++) {
            int r = rr + u;
            float4 A = sA[r];                 // broadcast LDS.128 (uniform r)
            float sx = px - A.x;
            float sy = py - A.y;
            float d2 = sx * sx + sy * sy;
            if (d2 > A.z) continue;           // ~99.8% rejected here

            float sz = pz - A.w;
            float4 B = sB[r];
            float4 C = sC[r];
            float lx = sx * B.x - sy * B.y;   // rotate into roi frame (angle = -ry)
            float ly = sx * B.y + sy * B.x;
            bool in_box = (lx > -B.z) && (lx < B.z) &&
                          (ly > -B.w) && (ly < B.w) &&
                          (fabsf(sz - C.x) <= C.x);
            if (!in_box) continue;

            int xi = min(OUTD - 1, max(0, (int)floorf((lx + B.z) / C.y)));
            int yi = min(OUTD - 1, max(0, (int)floorf((ly + B.w) / C.z)));
            int zi = min(OUTD - 1, max(0, (int)floorf(sz / C.w)));
            int rv = r * N_VOX + xi * (OUTD * OUTD) + yi * OUTD + zi;
            int c = atomicAdd(&d_count[rv], 1);
            if (c == 0) {                     // unique first inserter
                int qi = atomicAdd(&sQcnt, 1);         // smem, no L2 trip
                if (qi < QBUF) {
                    sQbuf[qi] = make_int2(rv, p);
                } else {                       // overflow fallback (never taken)
                    int g = atomicAdd(&d_qn, 1);
                    d_queue[g] = make_int2(rv, p);
                }
            } else if (c < KMAX) {
                d_list[rv * KMAX + c] = p;    // slots 1..KMAX-1
            }
        }
    }
    // Safety tail (never taken for this geometry: 23 <= 32 slots).
    for (; fi < NF4; fi += N_PTS) __stcs(&o4[fi], z);

    // Flush smem queue: one global atomic per block, coalesced copy-out.
    __syncthreads();
    int cnt = min(sQcnt, QBUF);
    if (t == 0) sGbase = atomicAdd(&d_qn, cnt);
    __syncthreads();
    int gbase = sGbase;
    for (int j = t; j < cnt; j += 256)
        d_queue[gbase + j] = sQbuf[j];
}

// ---------------------------------------------------------------------------
// Kernel 2: worklist pool with pid0 payload (R14 exact — profiled 12.5us at
// 92% occ). Warps grid-stride the ~16K queue entries. n==1 (~94%): chain is
// queue LDG -> feat LDG -> STG with 2-deep rotation prefetching the next
// entry's whole chain. n>=2: list slots 1..; n>KMAX: rescan fallback.
// Counts self-cleaned per entry; last block out resets d_qn/d_done.
// ---------------------------------------------------------------------------
__global__ __launch_bounds__(256, 6) void pool_kernel(
    const float* __restrict__ rois, const float* __restrict__ pts,
    const float* __restrict__ feat, float* __restrict__ out)
{
    int lane  = threadIdx.x & 31;
    int gwarp = blockIdx.x * 8 + (threadIdx.x >> 5);
    int qn    = d_qn;                          // uniform read

    int i = gwarp;
    int cRv = -1, cN = 0;
    float2 cV = make_float2(0.f, 0.f);
    if (i < qn) {
        int2 q = d_queue[i];
        cRv = q.x;
        cN  = d_count[q.x];                    // parallel with feat load
        cV  = ((const float2*)(feat + (size_t)q.y * NCH))[lane];
    }
    while (cRv >= 0) {
        // Prefetch next entry's whole chain.
        int nRv = -1, nN = 0;
        float2 nV = make_float2(0.f, 0.f);
        i += POOL_WARPS;
        if (i < qn) {
            int2 q = d_queue[i];
            nRv = q.x;
            nN  = d_count[q.x];
            nV  = ((const float2*)(feat + (size_t)q.y * NCH))[lane];
        }
        if (lane == 0) d_count[cRv] = 0;       // self-clean for next replay

        float mx0 = cV.x, mx1 = cV.y;          // n==1: row is the answer
        if (cN > 1) {
            int mm = min(cN, KMAX);
            const int* lst = &d_list[(size_t)cRv * KMAX];
            int4 q4 = *(const int4*)lst;       // slots 0..3 (slot0 unused)
            {
                float2 v1, v2, v3;
                if (mm > 1) v1 = ((const float2*)(feat + (size_t)q4.y * NCH))[lane];
                if (mm > 2) v2 = ((const float2*)(feat + (size_t)q4.z * NCH))[lane];
                if (mm > 3) v3 = ((const float2*)(feat + (size_t)q4.w * NCH))[lane];
                if (mm > 1) { mx0 = fmaxf(mx0, v1.x); mx1 = fmaxf(mx1, v1.y); }
                if (mm > 2) { mx0 = fmaxf(mx0, v2.x); mx1 = fmaxf(mx1, v2.y); }
                if (mm > 3) { mx0 = fmaxf(mx0, v3.x); mx1 = fmaxf(mx1, v3.y); }
            }
            for (int j = 4; j < mm; j++) {
                int pid = lst[j];
                float2 v = ((const float2*)(feat + (size_t)pid * NCH))[lane];
                mx0 = fmaxf(mx0, v.x);
                mx1 = fmaxf(mx1, v.y);
            }
            if (cN > KMAX) {
                // Correctness fallback (statistically never taken): rescan.
                int r = cRv / N_VOX, vox = cRv % N_VOX;
                int xi = vox / (OUTD * OUTD), yi = (vox / OUTD) % OUTD, zi = vox % OUTD;
                const float* R = rois + r * 7;
                float cx = R[0], cy = R[1], cz = R[2];
                float dx = R[3], dy = R[4], dz = R[5];
                float ry = R[6];
                float hdx = dx * 0.5f, hdy = dy * 0.5f, hdz = dz * 0.5f;
                float ca = cosf(-ry), sa = sinf(-ry);
                float vx = dx / (float)OUTD, vy = dy / (float)OUTD, vz = dz / (float)OUTD;
                for (int bb = 0; bb < N_PTS; bb += 32) {
                    int pp = bb + lane;
                    bool hit = false;
                    {
                        float sx = pts[3 * pp + 0] - cx;
                        float sy = pts[3 * pp + 1] - cy;
                        float szz = pts[3 * pp + 2] - cz;
                        float lx = sx * ca - sy * sa;
                        float ly = sx * sa + sy * ca;
                        if ((lx > -hdx) && (lx < hdx) && (ly > -hdy) && (ly < hdy) &&
                            (fabsf(szz - hdz) <= hdz)) {
                            int xa = min(OUTD - 1, max(0, (int)floorf((lx + hdx) / vx)));
                            int ya = min(OUTD - 1, max(0, (int)floorf((ly + hdy) / vy)));
                            int za = min(OUTD - 1, max(0, (int)floorf(szz / vz)));
                            hit = (xa == xi) && (ya == yi) && (za == zi);
                        }
                    }
                    unsigned mk = __ballot_sync(0xffffffffu, hit);
                    while (mk) {
                        int src = __ffs(mk) - 1;
                        mk &= mk - 1;
                        int pid = bb + src;
                        float2 v = ((const float2*)(feat + (size_t)pid * NCH))[lane];
                        mx0 = fmaxf(mx0, v.x);
                        mx1 = fmaxf(mx1, v.y);
                    }
                }
            }
        }

        __stcs(&((float2*)(out + (size_t)cRv * NCH))[lane], make_float2(mx0, mx1));

        cRv = nRv; cN = nN; cV = nV;           // rotate pipeline
    }

    // Last block out resets the worklist counter (race-free; ticket counter).
    __syncthreads();
    if (threadIdx.x == 0) {
        __threadfence();
        int ticket = atomicAdd(&d_done, 1);
        if (ticket == POOL_BLOCKS - 1) {
            d_qn = 0;
            d_done = 0;
        }
    }
}

// ---------------------------------------------------------------------------
extern "C" void kernel_launch(void* const* d_in, const int* in_sizes, int n_in,
                              void* d_out, int out_size)
{
    const float* rois = (const float*)d_in[0];       // (128, 7)
    const float* pts  = (const float*)d_in[1];       // (160000, 3)
    const float* feat = (const float*)d_in[2];       // (160000, 64)
    float* out = (float*)d_out;                      // (128, 12, 12, 12, 64)

    build_fill_kernel<<<N_PTS / 256, 256>>>(rois, pts, out); // fill+build+batched queue
    pool_kernel<<<POOL_BLOCKS, 256>>>(rois, pts, feat, out); // worklist pool (pid0 payload)
}

// round 16
// speedup vs baseline: 1.4452x; 1.0478x over previous
#include <cuda_runtime.h>
#include <math.h>
#include <float.h>

#define OUTD    12
#define N_VOX   1728              // 12*12*12
#define N_ROIS  128
#define N_PTS   160000
#define NCH     64
#define KMAX    64                // cap on points per (roi,voxel); fallback handles overflow
#define NRV     (N_ROIS * N_VOX)  // 221184
#define NF4     (NRV * NCH / 4)   // 3,538,944 float4s in output

#define GRID    (N_PTS / 256)     // 625 blocks; <= 5/SM resident (740 slots)
#define NWARPS  (GRID * 8)        // 5000 warps in pool phase
#define QBUF    512               // per-block smem queue (expected ~27 used)

static_assert(N_PTS % 256 == 0, "exact grid");

// Scratch (__device__ globals = sanctioned scratch; zero-initialized at load).
// Invariants restored every replay: d_count zeroed per entry in pool phase;
// d_qn/d_arrive/d_done reset by last block out.
__device__ int d_count[NRV];
__device__ __align__(16) int d_list[NRV * KMAX];   // slots 1.. (slot0 rides in queue)
__device__ int d_qn;
__device__ int d_arrive;
__device__ int d_done;
__device__ __align__(8) int2 d_queue[NRV];         // {rv, first_pid}

// ---------------------------------------------------------------------------
// ONE persistent kernel: phase 1 = interleaved zero-fill + build (+ smem-
// batched worklist), grid barrier (all 625 blocks resident by launch_bounds),
// phase 2 = worklist pool. Fusion removes the second kernel's launch floor
// and inter-kernel gap, and phase 2 hits L2-hot queue/count data.
// ---------------------------------------------------------------------------
__global__ __launch_bounds__(256, 5) void fused_kernel(
    const float* __restrict__ rois, const float* __restrict__ pts,
    const float* __restrict__ feat, float* __restrict__ out)
{
    __shared__ float4 sA[N_ROIS];  // {cx, cy, r2_margin, cz}
    __shared__ float4 sB[N_ROIS];  // {cosa, sina, hdx, hdy}
    __shared__ float4 sC[N_ROIS];  // {hdz, vx, vy, vz}
    __shared__ int2   sQbuf[QBUF];
    __shared__ int    sQcnt;
    __shared__ int    sGbase;

    int t = threadIdx.x;
    int lane = t & 31;
    int wid  = t >> 5;
    int p = blockIdx.x * 256 + t;             // always < N_PTS (exact grid)

    float px = pts[3 * p + 0];
    float py = pts[3 * p + 1];
    float pz = pts[3 * p + 2];

    if (t == 0) sQcnt = 0;
    if (t < N_ROIS) {
        const float* R = rois + t * 7;
        float cx = R[0], cy = R[1], cz = R[2];
        float dx = R[3], dy = R[4], dz = R[5];
        float ry = R[6];
        float hdx = dx * 0.5f, hdy = dy * 0.5f, hdz = dz * 0.5f;
        float r2  = (hdx * hdx + hdy * hdy) * 1.0002f + 1e-6f;  // conservative
        float ca  = cosf(-ry), sa = sinf(-ry);
        sA[t] = make_float4(cx, cy, r2, cz);
        sB[t] = make_float4(ca, sa, hdx, hdy);
        sC[t] = make_float4(hdz, dx / (float)OUTD, dy / (float)OUTD, dz / (float)OUTD);
    }
    __syncthreads();

    // ---------------- Phase 1: build + interleaved fill ----------------
    float4* o4 = (float4*)out;
    const float4 z = make_float4(0.f, 0.f, 0.f, 0.f);
    int fi = p;                                // fill cursor, stride N_PTS

    for (int rr = 0; rr < N_ROIS; rr += 4) {
        // One interleaved zero store per 4-ROI group: the store queue drains
        // under ~30 instr of compute, hiding the 56.6MB LTS drain.
        if (fi < NF4) { __stcs(&o4[fi], z); fi += N_PTS; }

        #pragma unroll
        for (int u = 0; u < 4; u++) {
            int r = rr + u;
            float4 A = sA[r];                 // broadcast LDS.128 (uniform r)
            float sx = px - A.x;
            float sy = py - A.y;
            float d2 = sx * sx + sy * sy;
            if (d2 > A.z) continue;           // ~99.8% rejected here

            float sz = pz - A.w;
            float4 B = sB[r];
            float4 C = sC[r];
            float lx = sx * B.x - sy * B.y;   // rotate into roi frame (angle = -ry)
            float ly = sx * B.y + sy * B.x;
            bool in_box = (lx > -B.z) && (lx < B.z) &&
                          (ly > -B.w) && (ly < B.w) &&
                          (fabsf(sz - C.x) <= C.x);
            if (!in_box) continue;

            int xi = min(OUTD - 1, max(0, (int)floorf((lx + B.z) / C.y)));
            int yi = min(OUTD - 1, max(0, (int)floorf((ly + B.w) / C.z)));
            int zi = min(OUTD - 1, max(0, (int)floorf(sz / C.w)));
            int rv = r * N_VOX + xi * (OUTD * OUTD) + yi * OUTD + zi;
            int c = atomicAdd(&d_count[rv], 1);
            if (c == 0) {                     // unique first inserter
                int qi = atomicAdd(&sQcnt, 1);        // smem, no L2 hotspot
                if (qi < QBUF) {
                    sQbuf[qi] = make_int2(rv, p);
                } else {                      // overflow fallback (never taken)
                    int g = atomicAdd(&d_qn, 1);
                    d_queue[g] = make_int2(rv, p);
                }
            } else if (c < KMAX) {
                d_list[rv * KMAX + c] = p;    // slots 1..KMAX-1
            }
        }
    }
    for (; fi < NF4; fi += N_PTS) __stcs(&o4[fi], z);   // safety tail

    // Flush smem queue: one global atomic per block, coalesced copy-out.
    __syncthreads();
    int cnt = min(sQcnt, QBUF);
    if (t == 0) sGbase = atomicAdd(&d_qn, cnt);
    __syncthreads();
    int gbase = sGbase;
    for (int j = t; j < cnt; j += 256)
        d_queue[gbase + j] = sQbuf[j];

    // ---------------- Grid barrier (all blocks resident) ----------------
    __threadfence();                           // release phase-1 writes
    __syncthreads();
    if (t == 0) {
        atomicAdd(&d_arrive, 1);
        volatile int* va = &d_arrive;
        while (*va < GRID) __nanosleep(64);
    }
    __syncthreads();
    __threadfence();                           // acquire phase-1 writes

    // ---------------- Phase 2: worklist pool ----------------
    int qn = d_qn;                             // final
    int i = blockIdx.x * 8 + wid;              // gwarp
    int cRv = -1, cN = 0;
    float2 cV = make_float2(0.f, 0.f);
    if (i < qn) {
        int2 q = d_queue[i];
        cRv = q.x;
        cN  = d_count[q.x];                    // parallel with feat load
        cV  = ((const float2*)(feat + (size_t)q.y * NCH))[lane];
    }
    while (cRv >= 0) {
        // Prefetch next entry's whole chain.
        int nRv = -1, nN = 0;
        float2 nV = make_float2(0.f, 0.f);
        i += NWARPS;
        if (i < qn) {
            int2 q = d_queue[i];
            nRv = q.x;
            nN  = d_count[q.x];
            nV  = ((const float2*)(feat + (size_t)q.y * NCH))[lane];
        }
        if (lane == 0) d_count[cRv] = 0;       // self-clean for next replay

        float mx0 = cV.x, mx1 = cV.y;          // n==1 (~94%): row is the answer
        if (cN > 1) {
            int mm = min(cN, KMAX);
            const int* lst = &d_list[(size_t)cRv * KMAX];
            int4 q4 = *(const int4*)lst;       // slots 0..3 (slot0 unused)
            {
                float2 v1, v2, v3;
                if (mm > 1) v1 = ((const float2*)(feat + (size_t)q4.y * NCH))[lane];
                if (mm > 2) v2 = ((const float2*)(feat + (size_t)q4.z * NCH))[lane];
                if (mm > 3) v3 = ((const float2*)(feat + (size_t)q4.w * NCH))[lane];
                if (mm > 1) { mx0 = fmaxf(mx0, v1.x); mx1 = fmaxf(mx1, v1.y); }
                if (mm > 2) { mx0 = fmaxf(mx0, v2.x); mx1 = fmaxf(mx1, v2.y); }
                if (mm > 3) { mx0 = fmaxf(mx0, v3.x); mx1 = fmaxf(mx1, v3.y); }
            }
            for (int j = 4; j < mm; j++) {
                int pid = lst[j];
                float2 v = ((const float2*)(feat + (size_t)pid * NCH))[lane];
                mx0 = fmaxf(mx0, v.x);
                mx1 = fmaxf(mx1, v.y);
            }
            if (cN > KMAX) {
                // Correctness fallback (statistically never taken): rescan.
                int r = cRv / N_VOX, vox = cRv % N_VOX;
                int xi = vox / (OUTD * OUTD), yi = (vox / OUTD) % OUTD, zi = vox % OUTD;
                const float* R = rois + r * 7;
                float cx = R[0], cy = R[1], cz = R[2];
                float dx = R[3], dy = R[4], dz = R[5];
                float ry = R[6];
                float hdx = dx * 0.5f, hdy = dy * 0.5f, hdz = dz * 0.5f;
                float ca = cosf(-ry), sa = sinf(-ry);
                float vx = dx / (float)OUTD, vy = dy / (float)OUTD, vz = dz / (float)OUTD;
                for (int bb = 0; bb < N_PTS; bb += 32) {
                    int pp = bb + lane;
                    bool hit = false;
                    {
                        float sx = pts[3 * pp + 0] - cx;
                        float sy = pts[3 * pp + 1] - cy;
                        float szz = pts[3 * pp + 2] - cz;
                        float lx = sx * ca - sy * sa;
                        float ly = sx * sa + sy * ca;
                        if ((lx > -hdx) && (lx < hdx) && (ly > -hdy) && (ly < hdy) &&
                            (fabsf(szz - hdz) <= hdz)) {
                            int xa = min(OUTD - 1, max(0, (int)floorf((lx + hdx) / vx)));
                            int ya = min(OUTD - 1, max(0, (int)floorf((ly + hdy) / vy)));
                            int za = min(OUTD - 1, max(0, (int)floorf(szz / vz)));
                            hit = (xa == xi) && (ya == yi) && (za == zi);
                        }
                    }
                    unsigned mk = __ballot_sync(0xffffffffu, hit);
                    while (mk) {
                        int src = __ffs(mk) - 1;
                        mk &= mk - 1;
                        int pid = bb + src;
                        float2 v = ((const float2*)(feat + (size_t)pid * NCH))[lane];
                        mx0 = fmaxf(mx0, v.x);
                        mx1 = fmaxf(mx1, v.y);
                    }
                }
            }
        }

        __stcs(&((float2*)(out + (size_t)cRv * NCH))[lane], make_float2(mx0, mx1));

        cRv = nRv; cN = nN; cV = nV;           // rotate pipeline
    }

    // Last block out resets all counters (race-free ticket).
    __syncthreads();
    if (t == 0) {
        __threadfence();
        int ticket = atomicAdd(&d_done, 1);
        if (ticket == GRID - 1) {
            d_qn = 0;
            d_arrive = 0;
            d_done = 0;
        }
    }
}

// ---------------------------------------------------------------------------
extern "C" void kernel_launch(void* const* d_in, const int* in_sizes, int n_in,
                              void* d_out, int out_size)
{
    const float* rois = (const float*)d_in[0];       // (128, 7)
    const float* pts  = (const float*)d_in[1];       // (160000, 3)
    const float* feat = (const float*)d_in[2];       // (160000, 64)
    float* out = (float*)d_out;                      // (128, 12, 12, 12, 64)

    fused_kernel<<<GRID, 256>>>(rois, pts, feat, out);   // single launch
}